// round 9
// baseline (speedup 1.0000x reference)
#include <cuda_runtime.h>
#include <cuda_fp16.h>
#include <cstdint>

// ============================================================================
// BinaryDense: out[8192,2048] = X[8192,2048] @ (W >= 0 ? 1 : 0)[2048,2048]
// Plain sm_100 target (no tcgen05). fp16 mma.sync HMMA GEMM, fp32 accum.
// R9 = R6 resubmit (R8 bench was an infra failure, kernel never ran):
// in-CTA split-K, 2 warpgroups with named barriers, plus the __syncthreads()
// before partial-sum smem reuse that fixes the R5 NaN WAR race.
// ============================================================================

#define B_DIM 8192
#define K_DIM 2048
#define N_DIM 2048

#define BM 128
#define BN 128
#define BK 64
#define STAGES 3
#define SPLITK 2
#define KHALF (K_DIM / SPLITK)         // 1024
#define KTILES_G (KHALF / BK)          // 16

#define A_STAGE_BYTES (BM * BK * 2)    // 16384
#define B_STAGE_BYTES (BN * BK * 2)    // 16384
#define STAGE_BYTES (A_STAGE_BYTES + B_STAGE_BYTES)  // 32768
#define GROUP_SMEM (STAGES * STAGE_BYTES)            // 98304
#define SMEM_TOTAL (2 * GROUP_SMEM)                  // 196608 (1 CTA/SM)
#define PART_OFF GROUP_SMEM            // group1 stage area reused for partials

#define CONVERT_BLOCKS 8192            // X: 8192*2048 / (256*8)
#define BIN_BLOCKS (64 * 64)           // W 32x32 tiles

// Scratch: fp16 X and binarized+transposed W (Wb is [N, K], K contiguous)
__device__ __align__(1024) __half g_Xh[(size_t)B_DIM * K_DIM];
__device__ __align__(1024) __half g_Wb[(size_t)N_DIM * K_DIM];

// ---------------------------------------------------------------------------
__device__ __forceinline__ uint32_t smem_u32(const void* p) {
    uint32_t a;
    asm("{ .reg .u64 t; cvta.to.shared.u64 t, %1; cvt.u32.u64 %0, t; }"
        : "=r"(a) : "l"(p));
    return a;
}

__device__ __forceinline__ void cp_async16(uint32_t dst, const void* src) {
    asm volatile("cp.async.cg.shared.global [%0], [%1], 16;"
                 :: "r"(dst), "l"(src) : "memory");
}
__device__ __forceinline__ void cp_commit() {
    asm volatile("cp.async.commit_group;" ::: "memory");
}
template <int N>
__device__ __forceinline__ void cp_wait() {
    asm volatile("cp.async.wait_group %0;" :: "n"(N) : "memory");
}

// Named barrier: 256 threads of one warpgroup (ids 1 and 2)
__device__ __forceinline__ void bar_group(int id) {
    asm volatile("bar.sync %0, %1;" :: "r"(id), "r"(256) : "memory");
}

__device__ __forceinline__ void ldsm_x4(uint32_t& r0, uint32_t& r1,
                                        uint32_t& r2, uint32_t& r3, uint32_t a) {
    asm volatile("ldmatrix.sync.aligned.m8n8.x4.shared.b16 {%0,%1,%2,%3}, [%4];"
                 : "=r"(r0), "=r"(r1), "=r"(r2), "=r"(r3) : "r"(a));
}

__device__ __forceinline__ void mma16816(float* d, const uint32_t* a,
                                         const uint32_t* b) {
    asm volatile(
        "mma.sync.aligned.m16n8k16.row.col.f32.f16.f16.f32 "
        "{%0,%1,%2,%3}, {%4,%5,%6,%7}, {%8,%9}, {%0,%1,%2,%3};"
        : "+f"(d[0]), "+f"(d[1]), "+f"(d[2]), "+f"(d[3])
        : "r"(a[0]), "r"(a[1]), "r"(a[2]), "r"(a[3]), "r"(b[0]), "r"(b[1]));
}

// ---------------------------------------------------------------------------
// Prep kernel (merged): blocks [0, CONVERT_BLOCKS) convert X fp32->fp16;
// blocks [CONVERT_BLOCKS, +BIN_BLOCKS) binarize+transpose W -> Wb[N,K] fp16.
// ---------------------------------------------------------------------------
__global__ void __launch_bounds__(256) prep_kernel(
    const float* __restrict__ x, const float* __restrict__ w,
    __half* __restrict__ xh, __half* __restrict__ wb) {
    int bid = blockIdx.x;
    int tid = threadIdx.x;
    if (bid < CONVERT_BLOCKS) {
        size_t i = ((size_t)bid * 256 + tid) * 8;
        float4 v0 = *reinterpret_cast<const float4*>(x + i);
        float4 v1 = *reinterpret_cast<const float4*>(x + i + 4);
        union { __half2 h[4]; uint4 u; } pk;
        pk.h[0] = __floats2half2_rn(v0.x, v0.y);
        pk.h[1] = __floats2half2_rn(v0.z, v0.w);
        pk.h[2] = __floats2half2_rn(v1.x, v1.y);
        pk.h[3] = __floats2half2_rn(v1.z, v1.w);
        *reinterpret_cast<uint4*>(xh + i) = pk.u;
    } else {
        __shared__ __half tile[32][33];
        int b = bid - CONVERT_BLOCKS;
        int n0 = (b & 63) * 32, k0 = (b >> 6) * 32;
        int tx = tid & 31, ty = tid >> 5;
#pragma unroll
        for (int r = 0; r < 32; r += 8) {
            float v = w[(size_t)(k0 + ty + r) * N_DIM + n0 + tx];
            tile[ty + r][tx] = __float2half(v < 0.0f ? 0.0f : 1.0f);
        }
        __syncthreads();
#pragma unroll
        for (int r = 0; r < 32; r += 8) {
            wb[(size_t)(n0 + ty + r) * K_DIM + k0 + tx] = tile[tx][ty + r];
        }
    }
}

// ---------------------------------------------------------------------------
// GEMM: 128x128 tile, 512 threads = 2 warpgroups x 8 warps.
// Group g: BK=64 3-stage cp.async pipeline over K[g*1024, (g+1)*1024),
// warp tiles 64x32 (2M x 4N), named-barrier sync (id g+1), own 96KB stages.
// Epilogue: sync; group1 partials -> smem (reusing its stage area);
// sync; group0 reduces + stores.
// Smem rows 128 B; SW128 swizzle: 16B-chunk ^= (row & 7).
// ---------------------------------------------------------------------------
__global__ void __launch_bounds__(512, 1)
bingemm_kernel(const __half* __restrict__ Xh, const __half* __restrict__ Wb,
               float* __restrict__ out) {
    extern __shared__ char smem[];
    const int tid = threadIdx.x;
    const int grp = tid >> 8;        // warpgroup 0/1
    const int tg = tid & 255;        // tid within group
    const int lane = tid & 31;
    const int widg = tg >> 5;        // warp id within group 0..7
    const uint32_t sb = smem_u32(smem) + (uint32_t)grp * GROUP_SMEM;

    const int wm = (widg >> 2) * 64;  // warp M offset
    const int wn = (widg & 3) * 32;   // warp N offset
    const int mBase = blockIdx.y * BM;
    const int nBase = blockIdx.x * BN;
    const int kBase = grp * KHALF;
    const int barId = grp + 1;

    // ---- cp.async precompute: 8 loads/thread/iter (4 A + 4 B) ----------
    const int row0 = tg >> 3;        // 0..31
    const int chunk = tg & 7;
    uint32_t dstA[4], dstB[4];
    const __half* srcA[4];
    const __half* srcB[4];
#pragma unroll
    for (int p = 0; p < 4; ++p) {
        int r = row0 + 32 * p;
        uint32_t sw = (uint32_t)(chunk ^ (r & 7)) * 16;
        dstA[p] = r * 128 + sw;
        dstB[p] = A_STAGE_BYTES + r * 128 + sw;
        srcA[p] = Xh + (size_t)(mBase + r) * K_DIM + kBase + chunk * 8;
        srcB[p] = Wb + (size_t)(nBase + r) * K_DIM + kBase + chunk * 8;
    }

    // ---- ldmatrix addresses (stage-relative; k16 step s => XOR s<<5) ---
    uint32_t aAddr[4];
#pragma unroll
    for (int mi = 0; mi < 4; ++mi) {
        int r = wm + mi * 16 + (lane & 15);
        int kc0 = lane >> 4;
        aAddr[mi] = (uint32_t)(r * 128 + ((kc0 ^ (r & 7)) * 16));
    }
    uint32_t bAddr[2];
#pragma unroll
    for (int j = 0; j < 2; ++j) {
        int r = wn + j * 16 + (lane & 7) + ((lane >> 4) & 1) * 8;
        int kc0 = (lane >> 3) & 1;
        bAddr[j] = (uint32_t)(A_STAGE_BYTES + r * 128 + ((kc0 ^ (r & 7)) * 16));
    }

    float acc[4][4][4];
#pragma unroll
    for (int mi = 0; mi < 4; ++mi)
#pragma unroll
        for (int ni = 0; ni < 4; ++ni)
#pragma unroll
            for (int e = 0; e < 4; ++e) acc[mi][ni][e] = 0.0f;

    // ---- prologue: fill STAGES-1 = 2 stages ----------------------------
#pragma unroll
    for (int s = 0; s < STAGES - 1; ++s) {
        uint32_t st = sb + s * STAGE_BYTES;
        int kOff = s * BK;
#pragma unroll
        for (int p = 0; p < 4; ++p) {
            cp_async16(st + dstA[p], srcA[p] + kOff);
            cp_async16(st + dstB[p], srcB[p] + kOff);
        }
        cp_commit();
    }

    // ---- mainloop: one group-barrier per BK=64 iteration (16 iters) ----
    int ldSlot = 0, pfSlot = STAGES - 1;
    for (int it = 0; it < KTILES_G; ++it) {
        cp_wait<STAGES - 2>();   // stage `it` resident
        bar_group(barId);        // group done reading stage it-1

        int pf = it + STAGES - 1;
        if (pf < KTILES_G) {     // prefetch into the slot freed by it-1
            uint32_t st = sb + pfSlot * STAGE_BYTES;
            int kOff = pf * BK;
#pragma unroll
            for (int p = 0; p < 4; ++p) {
                cp_async16(st + dstA[p], srcA[p] + kOff);
                cp_async16(st + dstB[p], srcB[p] + kOff);
            }
        }
        cp_commit();

        uint32_t stage = sb + ldSlot * STAGE_BYTES;
#pragma unroll
        for (int s = 0; s < 4; ++s) {       // four k16 steps per BK=64
            const uint32_t kx = (uint32_t)s << 5;   // XOR: chunk bits 1-2
            uint32_t a[4][4];
#pragma unroll
            for (int mi = 0; mi < 4; ++mi)
                ldsm_x4(a[mi][0], a[mi][1], a[mi][2], a[mi][3],
                        stage + (aAddr[mi] ^ kx));
            uint32_t b[2][4];
#pragma unroll
            for (int j = 0; j < 2; ++j)
                ldsm_x4(b[j][0], b[j][1], b[j][2], b[j][3],
                        stage + (bAddr[j] ^ kx));
#pragma unroll
            for (int mi = 0; mi < 4; ++mi)
#pragma unroll
                for (int ni = 0; ni < 4; ++ni)
                    mma16816(acc[mi][ni], a[mi], &b[ni >> 1][(ni & 1) * 2]);
        }

        if (++ldSlot == STAGES) ldSlot = 0;
        if (++pfSlot == STAGES) pfSlot = 0;
    }

    // ---- cross-group reduction -----------------------------------------
    // The partial buffer ALIASES group1's stage slots 0-1. A full CTA
    // barrier is REQUIRED before the stores: it guarantees every group-1
    // warp has finished its last ldmatrix reads of those slots (this was
    // the R5 NaN race).
    __syncthreads();

    float* part = reinterpret_cast<float*>(smem + PART_OFF);
    if (grp == 1) {
        // Layout [reg][thread]: word index = r*256 + tg (conflict-free).
#pragma unroll
        for (int mi = 0; mi < 4; ++mi)
#pragma unroll
            for (int ni = 0; ni < 4; ++ni)
#pragma unroll
                for (int e = 0; e < 4; ++e)
                    part[(mi * 16 + ni * 4 + e) * 256 + tg] = acc[mi][ni][e];
    }
    __syncthreads();
    if (grp == 0) {
#pragma unroll
        for (int mi = 0; mi < 4; ++mi)
#pragma unroll
            for (int ni = 0; ni < 4; ++ni)
#pragma unroll
                for (int e = 0; e < 4; ++e)
                    acc[mi][ni][e] += part[(mi * 16 + ni * 4 + e) * 256 + tg];

#pragma unroll
        for (int mi = 0; mi < 4; ++mi) {
#pragma unroll
            for (int h = 0; h < 2; ++h) {
                size_t row = (size_t)(mBase + wm + mi * 16 + h * 8 + (lane >> 2));
                float* p = out + row * N_DIM + nBase + wn + (lane & 3) * 2;
#pragma unroll
                for (int ni = 0; ni < 4; ++ni) {
                    float2 v = make_float2(acc[mi][ni][2 * h],
                                           acc[mi][ni][2 * h + 1]);
                    *reinterpret_cast<float2*>(p + ni * 8) = v;
                }
            }
        }
    }
}

// ---------------------------------------------------------------------------
extern "C" void kernel_launch(void* const* d_in, const int* in_sizes, int n_in,
                              void* d_out, int out_size) {
    const float* x = (const float*)d_in[0];   // [8192, 2048] fp32
    const float* w = (const float*)d_in[1];   // [2048, 2048] fp32
    float* out = (float*)d_out;               // [8192, 2048] fp32

    void *xh_ptr = nullptr, *wb_ptr = nullptr;
    cudaGetSymbolAddress(&xh_ptr, g_Xh);
    cudaGetSymbolAddress(&wb_ptr, g_Wb);

    prep_kernel<<<CONVERT_BLOCKS + BIN_BLOCKS, 256>>>(
        x, w, (__half*)xh_ptr, (__half*)wb_ptr);

    cudaFuncSetAttribute(bingemm_kernel,
                         cudaFuncAttributeMaxDynamicSharedMemorySize, SMEM_TOTAL);
    bingemm_kernel<<<dim3(N_DIM / BN, B_DIM / BM), 512, SMEM_TOTAL>>>(
        (const __half*)xh_ptr, (const __half*)wb_ptr, out);
}

// round 11
// speedup vs baseline: 1.0568x; 1.0568x over previous
#include <cuda_runtime.h>
#include <cuda_fp16.h>
#include <cstdint>

// ============================================================================
// BinaryDense: out[8192,2048] = X[8192,2048] @ (W >= 0 ? 1 : 0)[2048,2048]
// Plain sm_100 target (no tcgen05). fp16 mma.sync HMMA GEMM, fp32 accum.
// R11 = R10 + the missing iteration-0 barrier. R10's NaN: `if (it>0)`
// skipped ALL synchronization at it=0, so threads read slot 0 before other
// threads' prologue cp.async groups had landed (cp_wait is per-thread).
// A __syncthreads() on the it==0 path restores the R4 guarantee there;
// every later iteration is covered by the split named barrier (release
// implies all threads passed cp_wait + finished reading the recycled slot).
// ============================================================================

#define B_DIM 8192
#define K_DIM 2048
#define N_DIM 2048

#define BM 128
#define BN 128
#define BK 64
#define STAGES 3
#define KTILES (K_DIM / BK)          // 32

#define A_STAGE_BYTES (BM * BK * 2)  // 16384
#define B_STAGE_BYTES (BN * BK * 2)  // 16384
#define STAGE_BYTES (A_STAGE_BYTES + B_STAGE_BYTES)  // 32768
#define SMEM_TOTAL (STAGES * STAGE_BYTES)            // 98304 (x2 CTA = 192K)

#define BAR_CNT 512                  // 256 arrives + 256 syncs per phase

#define CONVERT_BLOCKS 8192          // X: 8192*2048 / (256*8)
#define BIN_BLOCKS (64 * 64)         // W 32x32 tiles

// Scratch: fp16 X and binarized+transposed W (Wb is [N, K], K contiguous)
__device__ __align__(1024) __half g_Xh[(size_t)B_DIM * K_DIM];
__device__ __align__(1024) __half g_Wb[(size_t)N_DIM * K_DIM];

// ---------------------------------------------------------------------------
__device__ __forceinline__ uint32_t smem_u32(const void* p) {
    uint32_t a;
    asm("{ .reg .u64 t; cvta.to.shared.u64 t, %1; cvt.u32.u64 %0, t; }"
        : "=r"(a) : "l"(p));
    return a;
}

__device__ __forceinline__ void cp_async16(uint32_t dst, const void* src) {
    asm volatile("cp.async.cg.shared.global [%0], [%1], 16;"
                 :: "r"(dst), "l"(src) : "memory");
}
__device__ __forceinline__ void cp_commit() {
    asm volatile("cp.async.commit_group;" ::: "memory");
}
template <int N>
__device__ __forceinline__ void cp_wait() {
    asm volatile("cp.async.wait_group %0;" :: "n"(N) : "memory");
}

__device__ __forceinline__ void bar_sync_cnt(int id, int cnt) {
    asm volatile("bar.sync %0, %1;" :: "r"(id), "r"(cnt) : "memory");
}
__device__ __forceinline__ void bar_arrive_cnt(int id, int cnt) {
    asm volatile("bar.arrive %0, %1;" :: "r"(id), "r"(cnt) : "memory");
}

__device__ __forceinline__ void ldsm_x4(uint32_t& r0, uint32_t& r1,
                                        uint32_t& r2, uint32_t& r3, uint32_t a) {
    asm volatile("ldmatrix.sync.aligned.m8n8.x4.shared.b16 {%0,%1,%2,%3}, [%4];"
                 : "=r"(r0), "=r"(r1), "=r"(r2), "=r"(r3) : "r"(a));
}

__device__ __forceinline__ void mma16816(float* d, const uint32_t* a,
                                         const uint32_t* b) {
    asm volatile(
        "mma.sync.aligned.m16n8k16.row.col.f32.f16.f16.f32 "
        "{%0,%1,%2,%3}, {%4,%5,%6,%7}, {%8,%9}, {%0,%1,%2,%3};"
        : "+f"(d[0]), "+f"(d[1]), "+f"(d[2]), "+f"(d[3])
        : "r"(a[0]), "r"(a[1]), "r"(a[2]), "r"(a[3]), "r"(b[0]), "r"(b[1]));
}

// ---------------------------------------------------------------------------
// Prep kernel (merged): blocks [0, CONVERT_BLOCKS) convert X fp32->fp16;
// blocks [CONVERT_BLOCKS, +BIN_BLOCKS) binarize+transpose W -> Wb[N,K] fp16.
// ---------------------------------------------------------------------------
__global__ void __launch_bounds__(256) prep_kernel(
    const float* __restrict__ x, const float* __restrict__ w,
    __half* __restrict__ xh, __half* __restrict__ wb) {
    int bid = blockIdx.x;
    int tid = threadIdx.x;
    if (bid < CONVERT_BLOCKS) {
        size_t i = ((size_t)bid * 256 + tid) * 8;
        float4 v0 = *reinterpret_cast<const float4*>(x + i);
        float4 v1 = *reinterpret_cast<const float4*>(x + i + 4);
        union { __half2 h[4]; uint4 u; } pk;
        pk.h[0] = __floats2half2_rn(v0.x, v0.y);
        pk.h[1] = __floats2half2_rn(v0.z, v0.w);
        pk.h[2] = __floats2half2_rn(v1.x, v1.y);
        pk.h[3] = __floats2half2_rn(v1.z, v1.w);
        *reinterpret_cast<uint4*>(xh + i) = pk.u;
    } else {
        __shared__ __half tile[32][33];
        int b = bid - CONVERT_BLOCKS;
        int n0 = (b & 63) * 32, k0 = (b >> 6) * 32;
        int tx = tid & 31, ty = tid >> 5;
#pragma unroll
        for (int r = 0; r < 32; r += 8) {
            float v = w[(size_t)(k0 + ty + r) * N_DIM + n0 + tx];
            tile[ty + r][tx] = __float2half(v < 0.0f ? 0.0f : 1.0f);
        }
        __syncthreads();
#pragma unroll
        for (int r = 0; r < 32; r += 8) {
            wb[(size_t)(n0 + ty + r) * K_DIM + k0 + tx] = tile[tx][ty + r];
        }
    }
}

// ---------------------------------------------------------------------------
// GEMM: 128x128 block tile, BK=64, 3-stage cp.async, 2 CTAs/SM.
// 256 threads = 8 warps (2 M x 4 N), 64x32 warp tiles.
// Stage-reuse sync = split named barrier (parity ids 1/2, count 512):
//   bar.arrive posted right after the step-3 ldmatrix of iter `it`
//   bar.sync   at iter `it+1`, after cp_wait, before the cp.async that
//              overwrites the slot read at iter `it`.
// Iteration 0 uses __syncthreads() (cross-thread prologue completion).
// Smem rows 128 B (64 halfs); SW128 swizzle: 16B-chunk ^= (row & 7).
// ---------------------------------------------------------------------------
__global__ void __launch_bounds__(256, 2)
bingemm_kernel(const __half* __restrict__ Xh, const __half* __restrict__ Wb,
               float* __restrict__ out) {
    extern __shared__ char smem[];
    const uint32_t sb = smem_u32(smem);

    const int tid = threadIdx.x;
    const int lane = tid & 31;
    const int wid = tid >> 5;
    const int wm = (wid >> 2) * 64;   // warp M offset (2 rows of warps)
    const int wn = (wid & 3) * 32;    // warp N offset (4 cols of warps)

    const int mBase = blockIdx.y * BM;
    const int nBase = blockIdx.x * BN;

    // ---- cp.async precompute: 8 loads/thread/iter (4 A + 4 B) ----------
    const int row0 = tid >> 3;              // 0..31
    const int chunk = tid & 7;
    uint32_t dstA[4], dstB[4];
    const __half* srcA[4];
    const __half* srcB[4];
#pragma unroll
    for (int p = 0; p < 4; ++p) {
        int r = row0 + 32 * p;
        uint32_t sw = (uint32_t)(chunk ^ (r & 7)) * 16;
        dstA[p] = r * 128 + sw;
        dstB[p] = A_STAGE_BYTES + r * 128 + sw;
        srcA[p] = Xh + (size_t)(mBase + r) * K_DIM + chunk * 8;
        srcB[p] = Wb + (size_t)(nBase + r) * K_DIM + chunk * 8;
    }

    // ---- ldmatrix addresses (stage-relative; k16 step s => XOR s<<5) ---
    uint32_t aAddr[4];
#pragma unroll
    for (int mi = 0; mi < 4; ++mi) {
        int r = wm + mi * 16 + (lane & 15);
        int kc0 = lane >> 4;
        aAddr[mi] = (uint32_t)(r * 128 + ((kc0 ^ (r & 7)) * 16));
    }
    uint32_t bAddr[2];
#pragma unroll
    for (int j = 0; j < 2; ++j) {
        int r = wn + j * 16 + (lane & 7) + ((lane >> 4) & 1) * 8;
        int kc0 = (lane >> 3) & 1;
        bAddr[j] = (uint32_t)(A_STAGE_BYTES + r * 128 + ((kc0 ^ (r & 7)) * 16));
    }

    float acc[4][4][4];
#pragma unroll
    for (int mi = 0; mi < 4; ++mi)
#pragma unroll
        for (int ni = 0; ni < 4; ++ni)
#pragma unroll
            for (int e = 0; e < 4; ++e) acc[mi][ni][e] = 0.0f;

    // ---- prologue: fill STAGES-1 = 2 stages ----------------------------
#pragma unroll
    for (int s = 0; s < STAGES - 1; ++s) {
        uint32_t st = sb + s * STAGE_BYTES;
        int kOff = s * BK;
#pragma unroll
        for (int p = 0; p < 4; ++p) {
            cp_async16(st + dstA[p], srcA[p] + kOff);
            cp_async16(st + dstB[p], srcB[p] + kOff);
        }
        cp_commit();
    }

    // ---- mainloop ------------------------------------------------------
    // Iter it reads slot it%3; its prefetch writes slot (it+2)%3, which was
    // last read at iter it-1 -> guarded by arrive@it-1 / sync@it.
    // The barrier release ALSO implies every thread passed cp_wait<1> at
    // this iteration, making all threads' cp.async data for the current
    // slot visible (bar.sync orders smem). it==0 needs __syncthreads().
    int ldSlot = 0, pfSlot = STAGES - 1;
    for (int it = 0; it < KTILES; ++it) {
        cp_wait<STAGES - 2>();              // own groups: stage `it` resident
        if (it > 0)
            bar_sync_cnt(1 + ((it - 1) & 1), BAR_CNT);
        else
            __syncthreads();                // cross-thread prologue visibility

        int pf = it + STAGES - 1;
        if (pf < KTILES) {                  // overwrite slot read at it-1
            uint32_t st = sb + pfSlot * STAGE_BYTES;
            int kOff = pf * BK;
#pragma unroll
            for (int p = 0; p < 4; ++p) {
                cp_async16(st + dstA[p], srcA[p] + kOff);
                cp_async16(st + dstB[p], srcB[p] + kOff);
            }
        }
        cp_commit();

        uint32_t stage = sb + ldSlot * STAGE_BYTES;
#pragma unroll
        for (int s = 0; s < 4; ++s) {       // four k16 steps per BK=64
            const uint32_t kx = (uint32_t)s << 5;   // XOR: chunk bits 1-2
            uint32_t a[4][4];
#pragma unroll
            for (int mi = 0; mi < 4; ++mi)
                ldsm_x4(a[mi][0], a[mi][1], a[mi][2], a[mi][3],
                        stage + (aAddr[mi] ^ kx));
            uint32_t b[2][4];
#pragma unroll
            for (int j = 0; j < 2; ++j)
                ldsm_x4(b[j][0], b[j][1], b[j][2], b[j][3],
                        stage + (bAddr[j] ^ kx));
            // All smem reads of this stage issued once step-3 ldsm are out;
            // post the arrive BEFORE the step-3 MMAs so the stage-reuse
            // wait overlaps with tensor work. Safe: the matching sync at
            // it+1 sits after each thread's step-3 MMAs (which consume the
            // ldsm results), so release => all reads complete.
            if (s == 3 && it + 1 < KTILES)
                bar_arrive_cnt(1 + (it & 1), BAR_CNT);
#pragma unroll
            for (int mi = 0; mi < 4; ++mi)
#pragma unroll
                for (int ni = 0; ni < 4; ++ni)
                    mma16816(acc[mi][ni], a[mi], &b[ni >> 1][(ni & 1) * 2]);
        }

        if (++ldSlot == STAGES) ldSlot = 0;
        if (++pfSlot == STAGES) pfSlot = 0;
    }

    // ---- epilogue: direct float2 stores (regs -> gmem, no smem reuse) --
#pragma unroll
    for (int mi = 0; mi < 4; ++mi) {
#pragma unroll
        for (int h = 0; h < 2; ++h) {
            size_t row = (size_t)(mBase + wm + mi * 16 + h * 8 + (lane >> 2));
            float* p = out + row * N_DIM + nBase + wn + (lane & 3) * 2;
#pragma unroll
            for (int ni = 0; ni < 4; ++ni) {
                float2 v = make_float2(acc[mi][ni][2 * h], acc[mi][ni][2 * h + 1]);
                *reinterpret_cast<float2*>(p + ni * 8) = v;
            }
        }
    }
}

// ---------------------------------------------------------------------------
extern "C" void kernel_launch(void* const* d_in, const int* in_sizes, int n_in,
                              void* d_out, int out_size) {
    const float* x = (const float*)d_in[0];   // [8192, 2048] fp32
    const float* w = (const float*)d_in[1];   // [2048, 2048] fp32
    float* out = (float*)d_out;               // [8192, 2048] fp32

    void *xh_ptr = nullptr, *wb_ptr = nullptr;
    cudaGetSymbolAddress(&xh_ptr, g_Xh);
    cudaGetSymbolAddress(&wb_ptr, g_Wb);

    prep_kernel<<<CONVERT_BLOCKS + BIN_BLOCKS, 256>>>(
        x, w, (__half*)xh_ptr, (__half*)wb_ptr);

    cudaFuncSetAttribute(bingemm_kernel,
                         cudaFuncAttributeMaxDynamicSharedMemorySize, SMEM_TOTAL);
    bingemm_kernel<<<dim3(N_DIM / BN, B_DIM / BM), 256, SMEM_TOTAL>>>(
        (const __half*)xh_ptr, (const __half*)wb_ptr, out);
}

// round 12
// speedup vs baseline: 1.0627x; 1.0056x over previous
#include <cuda_runtime.h>
#include <cuda_fp16.h>
#include <cstdint>

// ============================================================================
// BinaryDense: out[8192,2048] = X[8192,2048] @ (W >= 0 ? 1 : 0)[2048,2048]
// Plain sm_100 target (no tcgen05). fp16 mma.sync HMMA GEMM, fp32 accum.
// R12: 64x64 warp tiles (4 warps/CTA, 128 threads, 2x2), 2 CTAs/SM.
// Rationale: R4/R11 mainloop was smem-crossbar bound (LDSM 192KB + STS 64KB
// = 128 B/cyc = crossbar cap per 2048-cyc iter). 64x64 warp tiles halve
// LDSM bytes/MMA -> 96 B/cyc (75%), freeing the tensor pipe.
// ============================================================================

#define B_DIM 8192
#define K_DIM 2048
#define N_DIM 2048

#define BM 128
#define BN 128
#define BK 64
#define STAGES 3
#define KTILES (K_DIM / BK)          // 32

#define A_STAGE_BYTES (BM * BK * 2)  // 16384
#define B_STAGE_BYTES (BN * BK * 2)  // 16384
#define STAGE_BYTES (A_STAGE_BYTES + B_STAGE_BYTES)  // 32768
#define SMEM_TOTAL (STAGES * STAGE_BYTES)            // 98304 (x2 CTA = 192K)

#define CONVERT_BLOCKS 8192          // X: 8192*2048 / (256*8)
#define BIN_BLOCKS (64 * 64)         // W 32x32 tiles

// Scratch: fp16 X and binarized+transposed W (Wb is [N, K], K contiguous)
__device__ __align__(1024) __half g_Xh[(size_t)B_DIM * K_DIM];
__device__ __align__(1024) __half g_Wb[(size_t)N_DIM * K_DIM];

// ---------------------------------------------------------------------------
__device__ __forceinline__ uint32_t smem_u32(const void* p) {
    uint32_t a;
    asm("{ .reg .u64 t; cvta.to.shared.u64 t, %1; cvt.u32.u64 %0, t; }"
        : "=r"(a) : "l"(p));
    return a;
}

__device__ __forceinline__ void cp_async16(uint32_t dst, const void* src) {
    asm volatile("cp.async.cg.shared.global [%0], [%1], 16;"
                 :: "r"(dst), "l"(src) : "memory");
}
__device__ __forceinline__ void cp_commit() {
    asm volatile("cp.async.commit_group;" ::: "memory");
}
template <int N>
__device__ __forceinline__ void cp_wait() {
    asm volatile("cp.async.wait_group %0;" :: "n"(N) : "memory");
}

__device__ __forceinline__ void ldsm_x4(uint32_t& r0, uint32_t& r1,
                                        uint32_t& r2, uint32_t& r3, uint32_t a) {
    asm volatile("ldmatrix.sync.aligned.m8n8.x4.shared.b16 {%0,%1,%2,%3}, [%4];"
                 : "=r"(r0), "=r"(r1), "=r"(r2), "=r"(r3) : "r"(a));
}

__device__ __forceinline__ void mma16816(float* d, const uint32_t* a,
                                         const uint32_t* b) {
    asm volatile(
        "mma.sync.aligned.m16n8k16.row.col.f32.f16.f16.f32 "
        "{%0,%1,%2,%3}, {%4,%5,%6,%7}, {%8,%9}, {%0,%1,%2,%3};"
        : "+f"(d[0]), "+f"(d[1]), "+f"(d[2]), "+f"(d[3])
        : "r"(a[0]), "r"(a[1]), "r"(a[2]), "r"(a[3]), "r"(b[0]), "r"(b[1]));
}

// ---------------------------------------------------------------------------
// Prep kernel (merged): blocks [0, CONVERT_BLOCKS) convert X fp32->fp16;
// blocks [CONVERT_BLOCKS, +BIN_BLOCKS) binarize+transpose W -> Wb[N,K] fp16.
// ---------------------------------------------------------------------------
__global__ void __launch_bounds__(256) prep_kernel(
    const float* __restrict__ x, const float* __restrict__ w,
    __half* __restrict__ xh, __half* __restrict__ wb) {
    int bid = blockIdx.x;
    int tid = threadIdx.x;
    if (bid < CONVERT_BLOCKS) {
        size_t i = ((size_t)bid * 256 + tid) * 8;
        float4 v0 = *reinterpret_cast<const float4*>(x + i);
        float4 v1 = *reinterpret_cast<const float4*>(x + i + 4);
        union { __half2 h[4]; uint4 u; } pk;
        pk.h[0] = __floats2half2_rn(v0.x, v0.y);
        pk.h[1] = __floats2half2_rn(v0.z, v0.w);
        pk.h[2] = __floats2half2_rn(v1.x, v1.y);
        pk.h[3] = __floats2half2_rn(v1.z, v1.w);
        *reinterpret_cast<uint4*>(xh + i) = pk.u;
    } else {
        __shared__ __half tile[32][33];
        int b = bid - CONVERT_BLOCKS;
        int n0 = (b & 63) * 32, k0 = (b >> 6) * 32;
        int tx = tid & 31, ty = tid >> 5;
#pragma unroll
        for (int r = 0; r < 32; r += 8) {
            float v = w[(size_t)(k0 + ty + r) * N_DIM + n0 + tx];
            tile[ty + r][tx] = __float2half(v < 0.0f ? 0.0f : 1.0f);
        }
        __syncthreads();
#pragma unroll
        for (int r = 0; r < 32; r += 8) {
            wb[(size_t)(n0 + ty + r) * K_DIM + k0 + tx] = tile[tx][ty + r];
        }
    }
}

// ---------------------------------------------------------------------------
// GEMM: 128x128 block tile, BK=64, 3-stage cp.async, 2 CTAs/SM.
// 128 threads = 4 warps (2 M x 2 N), 64x64 warp tiles, 128 fp32 acc/thread.
// Plain __syncthreads per iteration (measured better than split barrier).
// Smem rows 128 B (64 halfs); SW128 swizzle: 16B-chunk ^= (row & 7).
// ---------------------------------------------------------------------------
__global__ void __launch_bounds__(128, 2)
bingemm_kernel(const __half* __restrict__ Xh, const __half* __restrict__ Wb,
               float* __restrict__ out) {
    extern __shared__ char smem[];
    const uint32_t sb = smem_u32(smem);

    const int tid = threadIdx.x;
    const int lane = tid & 31;
    const int wid = tid >> 5;          // 0..3
    const int wm = (wid >> 1) * 64;    // warp M offset (2 rows of warps)
    const int wn = (wid & 1) * 64;     // warp N offset (2 cols of warps)

    const int mBase = blockIdx.y * BM;
    const int nBase = blockIdx.x * BN;

    // ---- cp.async precompute: 16 loads/thread/iter (8 A + 8 B) ---------
    // 128 threads cover 16 rows x 8 chunks per pass; 8 passes for 128 rows.
    // (row0 & 7) is invariant across passes (stride 16), so the swizzle
    // offset and all addresses are base + compile-time-constant offsets.
    const int row0 = tid >> 3;              // 0..15
    const int chunk = tid & 7;
    const uint32_t sw = (uint32_t)(chunk ^ (row0 & 7)) * 16;
    const uint32_t dA0 = (uint32_t)row0 * 128 + sw;
    const uint32_t dB0 = A_STAGE_BYTES + dA0;
    const __half* gA = Xh + (size_t)(mBase + row0) * K_DIM + chunk * 8;
    const __half* gB = Wb + (size_t)(nBase + row0) * K_DIM + chunk * 8;

    // ---- ldmatrix addresses (stage-relative; k16 step s => XOR s<<5) ---
    uint32_t aAddr[4];
#pragma unroll
    for (int mi = 0; mi < 4; ++mi) {
        int r = wm + mi * 16 + (lane & 15);
        int kc0 = lane >> 4;
        aAddr[mi] = (uint32_t)(r * 128 + ((kc0 ^ (r & 7)) * 16));
    }
    uint32_t bAddr[4];
#pragma unroll
    for (int j = 0; j < 4; ++j) {
        int r = wn + j * 16 + (lane & 7) + ((lane >> 4) & 1) * 8;
        int kc0 = (lane >> 3) & 1;
        bAddr[j] = (uint32_t)(A_STAGE_BYTES + r * 128 + ((kc0 ^ (r & 7)) * 16));
    }

    float acc[4][8][4];
#pragma unroll
    for (int mi = 0; mi < 4; ++mi)
#pragma unroll
        for (int ni = 0; ni < 8; ++ni)
#pragma unroll
            for (int e = 0; e < 4; ++e) acc[mi][ni][e] = 0.0f;

    // ---- prologue: fill STAGES-1 = 2 stages ----------------------------
#pragma unroll
    for (int s = 0; s < STAGES - 1; ++s) {
        uint32_t st = sb + s * STAGE_BYTES;
        int kOff = s * BK;
#pragma unroll
        for (int p = 0; p < 8; ++p) {
            cp_async16(st + dA0 + p * (16 * 128), gA + (size_t)(16 * p) * K_DIM + kOff);
            cp_async16(st + dB0 + p * (16 * 128), gB + (size_t)(16 * p) * K_DIM + kOff);
        }
        cp_commit();
    }

    // ---- mainloop: one __syncthreads per BK=64 iteration ---------------
    int ldSlot = 0, pfSlot = STAGES - 1;
    for (int it = 0; it < KTILES; ++it) {
        cp_wait<STAGES - 2>();   // stage `it` resident (own groups)
        __syncthreads();         // cross-thread completion + stage it-1 free

        int pf = it + STAGES - 1;
        if (pf < KTILES) {       // prefetch into the slot freed by it-1
            uint32_t st = sb + pfSlot * STAGE_BYTES;
            int kOff = pf * BK;
#pragma unroll
            for (int p = 0; p < 8; ++p) {
                cp_async16(st + dA0 + p * (16 * 128),
                           gA + (size_t)(16 * p) * K_DIM + kOff);
                cp_async16(st + dB0 + p * (16 * 128),
                           gB + (size_t)(16 * p) * K_DIM + kOff);
            }
        }
        cp_commit();

        uint32_t stage = sb + ldSlot * STAGE_BYTES;
#pragma unroll
        for (int s = 0; s < 4; ++s) {       // four k16 steps per BK=64
            const uint32_t kx = (uint32_t)s << 5;   // XOR: chunk bits 1-2
            uint32_t a[4][4];
#pragma unroll
            for (int mi = 0; mi < 4; ++mi)
                ldsm_x4(a[mi][0], a[mi][1], a[mi][2], a[mi][3],
                        stage + (aAddr[mi] ^ kx));
            uint32_t b[4][4];
#pragma unroll
            for (int j = 0; j < 4; ++j)
                ldsm_x4(b[j][0], b[j][1], b[j][2], b[j][3],
                        stage + (bAddr[j] ^ kx));
#pragma unroll
            for (int mi = 0; mi < 4; ++mi)
#pragma unroll
                for (int ni = 0; ni < 8; ++ni)
                    mma16816(acc[mi][ni], a[mi], &b[ni >> 1][(ni & 1) * 2]);
        }

        if (++ldSlot == STAGES) ldSlot = 0;
        if (++pfSlot == STAGES) pfSlot = 0;
    }

    // ---- epilogue: direct float2 stores --------------------------------
#pragma unroll
    for (int mi = 0; mi < 4; ++mi) {
#pragma unroll
        for (int h = 0; h < 2; ++h) {
            size_t row = (size_t)(mBase + wm + mi * 16 + h * 8 + (lane >> 2));
            float* p = out + row * N_DIM + nBase + wn + (lane & 3) * 2;
#pragma unroll
            for (int ni = 0; ni < 8; ++ni) {
                float2 v = make_float2(acc[mi][ni][2 * h], acc[mi][ni][2 * h + 1]);
                *reinterpret_cast<float2*>(p + ni * 8) = v;
            }
        }
    }
}

// ---------------------------------------------------------------------------
extern "C" void kernel_launch(void* const* d_in, const int* in_sizes, int n_in,
                              void* d_out, int out_size) {
    const float* x = (const float*)d_in[0];   // [8192, 2048] fp32
    const float* w = (const float*)d_in[1];   // [2048, 2048] fp32
    float* out = (float*)d_out;               // [8192, 2048] fp32

    void *xh_ptr = nullptr, *wb_ptr = nullptr;
    cudaGetSymbolAddress(&xh_ptr, g_Xh);
    cudaGetSymbolAddress(&wb_ptr, g_Wb);

    prep_kernel<<<CONVERT_BLOCKS + BIN_BLOCKS, 256>>>(
        x, w, (__half*)xh_ptr, (__half*)wb_ptr);

    cudaFuncSetAttribute(bingemm_kernel,
                         cudaFuncAttributeMaxDynamicSharedMemorySize, SMEM_TOTAL);
    bingemm_kernel<<<dim3(N_DIM / BN, B_DIM / BM), 128, SMEM_TOTAL>>>(
        (const __half*)xh_ptr, (const __half*)wb_ptr, out);
}